// round 7
// baseline (speedup 1.0000x reference)
#include <cuda_runtime.h>

#define BB 2048
#define TT 512
#define II 64

// Scratch [t][g][b] as float4: index (t*3+g)*BB + b holds (xr_g, xz_g, xn_g, 0).
// 8 timesteps of pad beyond t=TT are NEVER written -> stay zero (device globals
// zero-init). Layer-1 / dummy lanes point at the pad with stride 0 so they read
// exact 0.0 every step, keeping the loop body branch-free and bit-exact.
__device__ float4 g_xw4[(size_t)(TT + 8) * 3 * BB];
#define PAD_OFF ((size_t)TT * 3 * BB)

__device__ __forceinline__ float sigm(float x) {
    return __fdividef(1.0f, 1.0f + __expf(-x));
}
__device__ __forceinline__ float tanh_fast(float x) {
    float xc = fmaxf(x, -20.0f);
    float e = __expf(-2.0f * xc);
    return __fdividef(1.0f - e, 1.0f + e);
}

// ---------------------------------------------------------------------------
// Phase A: block = 128 consecutive t of one b (32 KB contiguous x chunk).
// Stage coalesced into padded smem, then each thread computes one (b,t) row.
// ---------------------------------------------------------------------------
__global__ void __launch_bounds__(128) phaseA(
    const float* __restrict__ x,
    const float* __restrict__ W_ih0,
    const float* __restrict__ b_ih0)
{
    __shared__ float4 xs4[128][17];   // 17 = 16 + pad (breaks bank alignment)
    __shared__ float4 ws4[144];       // W_ih0 as [9][16] float4
    __shared__ float  bs[9];

    const int tx = threadIdx.x;
    for (int i = tx; i < 144; i += 128) ws4[i] = ((const float4*)W_ih0)[i];
    if (tx < 9) bs[tx] = b_ih0[tx];

    const int bb = blockIdx.x >> 2;          // batch element
    const int t0 = (blockIdx.x & 3) << 7;    // t chunk start

    const float4* xg = (const float4*)x + ((size_t)bb * TT + t0) * (II / 4);
#pragma unroll
    for (int q = 0; q < 16; q++) {
        int f = tx + (q << 7);               // coalesced: lanes consecutive
        xs4[f >> 4][f & 15] = xg[f];
    }
    __syncthreads();

    float acc[9];
#pragma unroll
    for (int g = 0; g < 9; g++) acc[g] = bs[g];

#pragma unroll
    for (int i = 0; i < 16; i++) {
        float4 xv = xs4[tx][i];
#pragma unroll
        for (int g = 0; g < 9; g++) {
            float4 wv = ws4[g * 16 + i];
            acc[g] = fmaf(xv.w, wv.w, fmaf(xv.z, wv.z,
                     fmaf(xv.y, wv.y, fmaf(xv.x, wv.x, acc[g]))));
        }
    }

    const int t = t0 + tx;
    float4* o = g_xw4 + (size_t)t * 3 * BB + bb;
    o[0]      = make_float4(acc[0], acc[3], acc[6], 0.f);
    o[BB]     = make_float4(acc[1], acc[4], acc[7], 0.f);
    o[2 * BB] = make_float4(acc[2], acc[5], acc[8], 0.f);
}

// ---------------------------------------------------------------------------
// Phase B: 8 lanes per batch element.
//   j = lane&7:  j in {0,1,2} -> layer 0, hidden index g=j
//                j in {3,4,5} -> layer 1 (one step behind), g=j-3
//                j in {6,7}   -> dummy (execute harmlessly, never read/stored)
// Each lane holds ONE scalar h component; trios exchanged via shfl.
// <<<128,128>>> -> 512 warps -> 1 warp on each of 512 SMSPs (128 SMs x 4).
// ---------------------------------------------------------------------------
__global__ void __launch_bounds__(128, 1) gru_rec(
    const float* __restrict__ W_hh0, const float* __restrict__ b_hh0,
    const float* __restrict__ W_ih1, const float* __restrict__ b_ih1,
    const float* __restrict__ W_hh1, const float* __restrict__ b_hh1,
    float* __restrict__ out)
{
    const int tid  = blockIdx.x * 128 + threadIdx.x;
    const int lane = threadIdx.x & 31;
    const int j    = lane & 7;
    const int base = lane & ~7;          // group start lane
    const int g    = j % 3;              // hidden index (dummies alias 0/1)
    const bool l1  = (j >= 3);
    const int e    = tid >> 3;           // batch element

    // This lane's 3 gate rows {g, 3+g, 6+g} of its own layer's weights.
    // Input-side weights zeroed on layer-0 lanes (their ih must be exact 0).
    const float* whh = l1 ? W_hh1 : W_hh0;
    const float* bhh = l1 ? b_hh1 : b_hh0;
    float wh[3][3], wi[3][3], bh3[3], bi3[3];
#pragma unroll
    for (int q = 0; q < 3; q++) {
        int row = q * 3 + g;
        bh3[q] = __ldg(bhh + row);
        bi3[q] = l1 ? __ldg(b_ih1 + row) : 0.f;
#pragma unroll
        for (int k = 0; k < 3; k++) {
            wh[q][k] = __ldg(whh + row * 3 + k);
            wi[q][k] = l1 ? __ldg(W_ih1 + row * 3 + k) : 0.f;
        }
    }

    float h = 0.f;

    // Layer-0 lanes walk real scratch; others sit on the zero pad (stride 0).
    const size_t  xstr = l1 ? 0 : (size_t)(3 * BB);
    const float4* xb   = g_xw4 + (l1 ? PAD_OFF : ((size_t)g * BB + e));

    float4 buf[4];
#pragma unroll
    for (int s = 0; s < 4; s++) buf[s] = xb[(size_t)s * xstr];

    const int own = base + (l1 ? 3 : 0);
    const unsigned FULL = 0xffffffffu;

#pragma unroll 4
    for (int t = 0; t < TT; t++) {
        // h0 trio (for layer-1 input matvec) and own-layer trio (for gh).
        float a0 = __shfl_sync(FULL, h, base + 0);
        float a1 = __shfl_sync(FULL, h, base + 1);
        float a2 = __shfl_sync(FULL, h, base + 2);
        float o0 = __shfl_sync(FULL, h, own + 0);
        float o1 = __shfl_sync(FULL, h, own + 1);
        float o2 = __shfl_sync(FULL, h, own + 2);

        float4 b4 = buf[t & 3];
        buf[t & 3] = xb[(size_t)(t + 4) * xstr];   // 4-deep; pad beyond T

        float ghr = fmaf(wh[0][2], o2, fmaf(wh[0][1], o1, fmaf(wh[0][0], o0, bh3[0])));
        float ghz = fmaf(wh[1][2], o2, fmaf(wh[1][1], o1, fmaf(wh[1][0], o0, bh3[1])));
        float ghn = fmaf(wh[2][2], o2, fmaf(wh[2][1], o1, fmaf(wh[2][0], o0, bh3[2])));
        // layer0: wi/bi==0 -> ih==0, b4 real.  layer1: b4==0, ih real.
        float xr = fmaf(wi[0][2], a2, fmaf(wi[0][1], a1, fmaf(wi[0][0], a0, bi3[0]))) + b4.x;
        float xz = fmaf(wi[1][2], a2, fmaf(wi[1][1], a1, fmaf(wi[1][0], a0, bi3[1]))) + b4.y;
        float xn = fmaf(wi[2][2], a2, fmaf(wi[2][1], a1, fmaf(wi[2][0], a0, bi3[2]))) + b4.z;

        float r  = sigm(xr + ghr);
        float z  = sigm(xz + ghz);
        float n  = tanh_fast(fmaf(r, ghn, xn));
        float hn = fmaf(z, h - n, n);

        // Layer-1 lanes' t=0 step is the pipeline bubble: keep h1 = 0.
        h = (l1 && t == 0) ? 0.f : hn;
    }

    // Epilogue: layer-1 consumes h0^{T-1}. Layer-0 result discarded.
    {
        float a0 = __shfl_sync(FULL, h, base + 0);
        float a1 = __shfl_sync(FULL, h, base + 1);
        float a2 = __shfl_sync(FULL, h, base + 2);
        float o0 = __shfl_sync(FULL, h, own + 0);
        float o1 = __shfl_sync(FULL, h, own + 1);
        float o2 = __shfl_sync(FULL, h, own + 2);

        float ghr = fmaf(wh[0][2], o2, fmaf(wh[0][1], o1, fmaf(wh[0][0], o0, bh3[0])));
        float ghz = fmaf(wh[1][2], o2, fmaf(wh[1][1], o1, fmaf(wh[1][0], o0, bh3[1])));
        float ghn = fmaf(wh[2][2], o2, fmaf(wh[2][1], o1, fmaf(wh[2][0], o0, bh3[2])));
        float xr = fmaf(wi[0][2], a2, fmaf(wi[0][1], a1, fmaf(wi[0][0], a0, bi3[0])));
        float xz = fmaf(wi[1][2], a2, fmaf(wi[1][1], a1, fmaf(wi[1][0], a0, bi3[1])));
        float xn = fmaf(wi[2][2], a2, fmaf(wi[2][1], a1, fmaf(wi[2][0], a0, bi3[2])));

        float r  = sigm(xr + ghr);
        float z  = sigm(xz + ghz);
        float n  = tanh_fast(fmaf(r, ghn, xn));
        float hn = fmaf(z, h - n, n);
        h = l1 ? hn : h;
    }

    if (j >= 3 && j < 6)
        out[e * 3 + g] = h;
}

extern "C" void kernel_launch(void* const* d_in, const int* in_sizes, int n_in,
                              void* d_out, int out_size)
{
    const float* x     = (const float*)d_in[0];
    const float* W_ih0 = (const float*)d_in[1];
    const float* W_hh0 = (const float*)d_in[2];
    const float* b_ih0 = (const float*)d_in[3];
    const float* b_hh0 = (const float*)d_in[4];
    const float* W_ih1 = (const float*)d_in[5];
    const float* W_hh1 = (const float*)d_in[6];
    const float* b_ih1 = (const float*)d_in[7];
    const float* b_hh1 = (const float*)d_in[8];
    float* out = (float*)d_out;

    // 4 chunks of 128 t per batch element
    phaseA<<<BB * 4, 128>>>(x, W_ih0, b_ih0);
    // 8 lanes per element: 16384 threads -> 128 blocks x 4 warps -> 512 SMSPs
    gru_rec<<<(BB * 8) / 128, 128>>>(W_hh0, b_hh0, W_ih1, b_ih1, W_hh1, b_hh1, out);
}

// round 9
// speedup vs baseline: 1.5590x; 1.5590x over previous
#include <cuda_runtime.h>

#define BB 2048
#define TT 512
#define II 64

// Scratch [t][g][b] as float4: index (t*3+g)*BB + b holds (xr_g, xz_g, xn_g, 0).
// 8 timesteps of pad beyond t=TT are NEVER written -> stay zero (device globals
// zero-init). Layer-1 / dummy lanes point at the pad with stride 0 so they read
// exact 0.0 every step, keeping the loop body branch-free and bit-exact.
__device__ float4 g_xw4[(size_t)(TT + 8) * 3 * BB];
#define PAD_OFF ((size_t)TT * 3 * BB)

__device__ __forceinline__ float sigm(float x) {
    return __fdividef(1.0f, 1.0f + __expf(-x));
}
__device__ __forceinline__ float tanh_fast(float x) {
    float xc = fmaxf(x, -20.0f);
    float e = __expf(-2.0f * xc);
    return __fdividef(1.0f - e, 1.0f + e);
}

// ---------------------------------------------------------------------------
// Phase A (r3/r6 form): one thread per (b,t); lanes consecutive in b so the
// three float4 scratch stores are perfectly coalesced.
// ---------------------------------------------------------------------------
__global__ void __launch_bounds__(256) phaseA(
    const float* __restrict__ x,
    const float* __restrict__ W_ih0,
    const float* __restrict__ b_ih0)
{
    __shared__ float4 Ws4[9 * 16];
    __shared__ float bs[9];
    if (threadIdx.x < 144) Ws4[threadIdx.x] = ((const float4*)W_ih0)[threadIdx.x];
    if (threadIdx.x < 9)   bs[threadIdx.x] = b_ih0[threadIdx.x];
    __syncthreads();

    int idx = blockIdx.x * blockDim.x + threadIdx.x;   // 0 .. B*T-1
    int b = idx & (BB - 1);
    int t = idx >> 11;

    const float4* xp = reinterpret_cast<const float4*>(x + ((size_t)b * TT + t) * II);

    float acc[9];
#pragma unroll
    for (int g = 0; g < 9; g++) acc[g] = bs[g];

#pragma unroll
    for (int i = 0; i < II / 4; i++) {
        float4 xv = xp[i];
#pragma unroll
        for (int g = 0; g < 9; g++) {
            float4 wv = Ws4[g * 16 + i];
            acc[g] = fmaf(xv.w, wv.w, fmaf(xv.z, wv.z,
                     fmaf(xv.y, wv.y, fmaf(xv.x, wv.x, acc[g]))));
        }
    }

    float4* o = g_xw4 + (size_t)t * 3 * BB + b;
    o[0]      = make_float4(acc[0], acc[3], acc[6], 0.f);
    o[BB]     = make_float4(acc[1], acc[4], acc[7], 0.f);
    o[2 * BB] = make_float4(acc[2], acc[5], acc[8], 0.f);
}

// ---------------------------------------------------------------------------
// Phase B: 8 lanes per batch element (r7 layout), depth-8 prefetch ring.
//   j = lane&7:  {0,1,2} -> layer 0 (hidden g=j); {3,4,5} -> layer 1, one
//   step behind (g=j-3); {6,7} dummy. One scalar h per lane; shfl exchange.
// <<<128,128>>> -> 512 warps -> 1 warp on each of 512 SMSPs.
// ---------------------------------------------------------------------------
__global__ void __launch_bounds__(128, 1) gru_rec(
    const float* __restrict__ W_hh0, const float* __restrict__ b_hh0,
    const float* __restrict__ W_ih1, const float* __restrict__ b_ih1,
    const float* __restrict__ W_hh1, const float* __restrict__ b_hh1,
    float* __restrict__ out)
{
    const int tid  = blockIdx.x * 128 + threadIdx.x;
    const int lane = threadIdx.x & 31;
    const int j    = lane & 7;
    const int base = lane & ~7;
    const int g    = j % 3;
    const bool l1  = (j >= 3);
    const int e    = tid >> 3;

    const float* whh = l1 ? W_hh1 : W_hh0;
    const float* bhh = l1 ? b_hh1 : b_hh0;
    float wh[3][3], wi[3][3], bh3[3], bi3[3];
#pragma unroll
    for (int q = 0; q < 3; q++) {
        int row = q * 3 + g;
        bh3[q] = __ldg(bhh + row);
        bi3[q] = l1 ? __ldg(b_ih1 + row) : 0.f;
#pragma unroll
        for (int k = 0; k < 3; k++) {
            wh[q][k] = __ldg(whh + row * 3 + k);
            wi[q][k] = l1 ? __ldg(W_ih1 + row * 3 + k) : 0.f;
        }
    }

    float h = 0.f;

    // Layer-0 lanes walk real scratch; others sit on the zero pad (stride 0).
    const size_t  xstr = l1 ? 0 : (size_t)(3 * BB);
    const float4* xb   = g_xw4 + (l1 ? PAD_OFF : ((size_t)g * BB + e));

    // 8-deep ring: reload distance = 8 iterations (~1200 cyc) >> DRAM 577.
    float4 buf[8];
#pragma unroll
    for (int s = 0; s < 8; s++) buf[s] = xb[(size_t)s * xstr];

    const int own = base + (l1 ? 3 : 0);
    const unsigned FULL = 0xffffffffu;

#pragma unroll 8
    for (int t = 0; t < TT; t++) {
        // Consume the 8-iteration-old slot; refill it first (early issue).
        float4 b4 = buf[t & 7];
        buf[t & 7] = xb[(size_t)(t + 8) * xstr];   // t+8 <= 519, inside pad

        float a0 = __shfl_sync(FULL, h, base + 0);
        float a1 = __shfl_sync(FULL, h, base + 1);
        float a2 = __shfl_sync(FULL, h, base + 2);
        float o0 = __shfl_sync(FULL, h, own + 0);
        float o1 = __shfl_sync(FULL, h, own + 1);
        float o2 = __shfl_sync(FULL, h, own + 2);

        float ghr = fmaf(wh[0][2], o2, fmaf(wh[0][1], o1, fmaf(wh[0][0], o0, bh3[0])));
        float ghz = fmaf(wh[1][2], o2, fmaf(wh[1][1], o1, fmaf(wh[1][0], o0, bh3[1])));
        float ghn = fmaf(wh[2][2], o2, fmaf(wh[2][1], o1, fmaf(wh[2][0], o0, bh3[2])));
        // layer0: wi/bi==0 -> ih==0, b4 real.  layer1: b4==0, ih real.
        float xr = fmaf(wi[0][2], a2, fmaf(wi[0][1], a1, fmaf(wi[0][0], a0, bi3[0]))) + b4.x;
        float xz = fmaf(wi[1][2], a2, fmaf(wi[1][1], a1, fmaf(wi[1][0], a0, bi3[1]))) + b4.y;
        float xn = fmaf(wi[2][2], a2, fmaf(wi[2][1], a1, fmaf(wi[2][0], a0, bi3[2]))) + b4.z;

        float r  = sigm(xr + ghr);
        float z  = sigm(xz + ghz);
        float n  = tanh_fast(fmaf(r, ghn, xn));
        float hn = fmaf(z, h - n, n);

        // Layer-1 lanes' t=0 step is the pipeline bubble: keep h1 = 0.
        h = (l1 && t == 0) ? 0.f : hn;
    }

    // Epilogue: layer-1 consumes h0^{T-1}. Layer-0 result discarded.
    {
        float a0 = __shfl_sync(FULL, h, base + 0);
        float a1 = __shfl_sync(FULL, h, base + 1);
        float a2 = __shfl_sync(FULL, h, base + 2);
        float o0 = __shfl_sync(FULL, h, own + 0);
        float o1 = __shfl_sync(FULL, h, own + 1);
        float o2 = __shfl_sync(FULL, h, own + 2);

        float ghr = fmaf(wh[0][2], o2, fmaf(wh[0][1], o1, fmaf(wh[0][0], o0, bh3[0])));
        float ghz = fmaf(wh[1][2], o2, fmaf(wh[1][1], o1, fmaf(wh[1][0], o0, bh3[1])));
        float ghn = fmaf(wh[2][2], o2, fmaf(wh[2][1], o1, fmaf(wh[2][0], o0, bh3[2])));
        float xr = fmaf(wi[0][2], a2, fmaf(wi[0][1], a1, fmaf(wi[0][0], a0, bi3[0])));
        float xz = fmaf(wi[1][2], a2, fmaf(wi[1][1], a1, fmaf(wi[1][0], a0, bi3[1])));
        float xn = fmaf(wi[2][2], a2, fmaf(wi[2][1], a1, fmaf(wi[2][0], a0, bi3[2])));

        float r  = sigm(xr + ghr);
        float z  = sigm(xz + ghz);
        float n  = tanh_fast(fmaf(r, ghn, xn));
        float hn = fmaf(z, h - n, n);
        h = l1 ? hn : h;
    }

    if (j >= 3 && j < 6)
        out[e * 3 + g] = h;
}

extern "C" void kernel_launch(void* const* d_in, const int* in_sizes, int n_in,
                              void* d_out, int out_size)
{
    const float* x     = (const float*)d_in[0];
    const float* W_ih0 = (const float*)d_in[1];
    const float* W_hh0 = (const float*)d_in[2];
    const float* b_ih0 = (const float*)d_in[3];
    const float* b_hh0 = (const float*)d_in[4];
    const float* W_ih1 = (const float*)d_in[5];
    const float* W_hh1 = (const float*)d_in[6];
    const float* b_ih1 = (const float*)d_in[7];
    const float* b_hh1 = (const float*)d_in[8];
    float* out = (float*)d_out;

    phaseA<<<(BB * TT) / 256, 256>>>(x, W_ih0, b_ih0);
    gru_rec<<<(BB * 8) / 128, 128>>>(W_hh0, b_hh0, W_ih1, b_ih1, W_hh1, b_hh1, out);
}

// round 11
// speedup vs baseline: 1.6862x; 1.0815x over previous
#include <cuda_runtime.h>

#define BB 2048
#define TT 512
#define II 64

// Scratch [t][g][b] as float4: index (t*3+g)*BB + b holds (xr_g, xz_g, xn_g, 0).
// 8 timesteps of pad beyond t=TT are NEVER written -> stay zero; dummy lanes
// point at the pad with stride 0.
__device__ float4 g_xw4[(size_t)(TT + 8) * 3 * BB];
#define PAD_OFF ((size_t)TT * 3 * BB)

__device__ __forceinline__ float sigm(float x) {
    return __fdividef(1.0f, 1.0f + __expf(-x));
}
__device__ __forceinline__ float tanh_fast(float x) {
    float xc = fmaxf(x, -20.0f);
    float e = __expf(-2.0f * xc);
    return __fdividef(1.0f - e, 1.0f + e);
}

// ---------------------------------------------------------------------------
// Phase A: 2D tile, 16 b x 8 t per block, 128 threads = one per (b,t) cell.
// Loads: per-b contiguous 2KB chunks, fully coalesced into padded smem.
// Stores: staged in smem, then written lanes-consecutive-in-b to match the
// [t][g][b] scratch layout.
// ---------------------------------------------------------------------------
__global__ void __launch_bounds__(128) phaseA(
    const float* __restrict__ x,
    const float* __restrict__ W_ih0,
    const float* __restrict__ b_ih0)
{
    __shared__ float4 xs[16 * 129];   // [b][8t * 16f4], b-stride 129 (pad 1)
    __shared__ float4 os[24 * 16];    // [(t*3+g)][b]
    __shared__ float4 ws4[144];       // W_ih0 as [9][16] float4
    __shared__ float  bs[9];

    const int tx = threadIdx.x;
    if (tx < 128) ws4[tx] = ((const float4*)W_ih0)[tx];
    if (tx < 16)  ws4[128 + tx] = ((const float4*)W_ih0)[128 + tx];
    if (tx < 9)   bs[tx] = b_ih0[tx];

    const int b0 = (blockIdx.x >> 6) << 4;   // 128 b-tiles
    const int t0 = (blockIdx.x & 63) << 3;   // 64 t-tiles

    const float4* xg = (const float4*)x;
#pragma unroll
    for (int c = 0; c < 16; c++) {
        int f   = (c << 7) + tx;             // 0..2047
        int bl  = f >> 7;                    // local b (128 f4 per b-chunk)
        int off = f & 127;                   // within the 8t x 16f4 chunk
        xs[bl * 129 + off] = xg[((size_t)(b0 + bl) * TT + t0) * 16 + off];
    }
    __syncthreads();

    const int b_loc = tx & 15;
    const int t_loc = tx >> 4;               // 0..7

    float acc[9];
#pragma unroll
    for (int g = 0; g < 9; g++) acc[g] = bs[g];

#pragma unroll
    for (int i = 0; i < 16; i++) {
        float4 xv = xs[b_loc * 129 + t_loc * 16 + i];
#pragma unroll
        for (int g = 0; g < 9; g++) {
            float4 wv = ws4[g * 16 + i];
            acc[g] = fmaf(xv.w, wv.w, fmaf(xv.z, wv.z,
                     fmaf(xv.y, wv.y, fmaf(xv.x, wv.x, acc[g]))));
        }
    }

#pragma unroll
    for (int g = 0; g < 3; g++)
        os[(t_loc * 3 + g) * 16 + b_loc] =
            make_float4(acc[g], acc[3 + g], acc[6 + g], 0.f);
    __syncthreads();

    // 384 float4 out, 128 threads x 3 rounds, lanes consecutive in b.
#pragma unroll
    for (int r = 0; r < 3; r++) {
        int f    = r * 128 + tx;
        int pair = f >> 4;                   // t_loc*3 + g  (0..23)
        int bl   = f & 15;
        int tt   = pair / 3, gg = pair % 3;
        g_xw4[((size_t)(t0 + tt) * 3 + gg) * BB + b0 + bl] = os[pair * 16 + bl];
    }
}

// ---------------------------------------------------------------------------
// Phase B: 4 lanes per element; lane j in {0,1,2} owns hidden index g=j of
// BOTH layers (hA = h0[g], hB = h1[g], L1 one step behind); j=3 dummy.
// Two independent activation chains per lane overlap in-warp (ILP).
// 8192 threads -> 256 blocks x 1 warp, spread over all SMs.
// ---------------------------------------------------------------------------
__global__ void __launch_bounds__(32, 1) gru_rec(
    const float* __restrict__ W_hh0, const float* __restrict__ b_hh0,
    const float* __restrict__ W_ih1, const float* __restrict__ b_ih1,
    const float* __restrict__ W_hh1, const float* __restrict__ b_hh1,
    float* __restrict__ out)
{
    const int tid   = blockIdx.x * 32 + threadIdx.x;
    const int lane  = threadIdx.x;
    const int j     = lane & 3;
    const int base  = lane & ~3;
    const bool dum  = (j == 3);
    const int g     = dum ? 0 : j;
    const int e     = tid >> 2;

    // Rows {g, 3+g, 6+g} of each weight matrix (q = gate type: r,z,n).
    float wh0[3][3], wi1[3][3], wh1[3][3], bh0[3], bi1[3], bh1[3];
#pragma unroll
    for (int q = 0; q < 3; q++) {
        int row = q * 3 + g;
        bh0[q] = __ldg(b_hh0 + row);
        bi1[q] = __ldg(b_ih1 + row);
        bh1[q] = __ldg(b_hh1 + row);
#pragma unroll
        for (int k = 0; k < 3; k++) {
            wh0[q][k] = __ldg(W_hh0 + row * 3 + k);
            wi1[q][k] = __ldg(W_ih1 + row * 3 + k);
            wh1[q][k] = __ldg(W_hh1 + row * 3 + k);
        }
    }

    float hA = 0.f;   // h0[g]
    float hB = 0.f;   // h1[g]

    const size_t  xstr = dum ? 0 : (size_t)(3 * BB);
    const float4* xb   = g_xw4 + (dum ? PAD_OFF : ((size_t)g * BB + e));

    float4 buf[8];
#pragma unroll
    for (int s = 0; s < 8; s++) buf[s] = xb[(size_t)s * xstr];

    const unsigned FULL = 0xffffffffu;

#pragma unroll 8
    for (int t = 0; t < TT; t++) {
        float4 b4 = buf[t & 7];
        buf[t & 7] = xb[(size_t)(t + 8) * xstr];   // t+8 <= 519, inside pad

        float a0 = __shfl_sync(FULL, hA, base + 0);   // h0^{t-1}
        float a1 = __shfl_sync(FULL, hA, base + 1);
        float a2 = __shfl_sync(FULL, hA, base + 2);
        float c0 = __shfl_sync(FULL, hB, base + 0);   // h1^{t-2}
        float c1 = __shfl_sync(FULL, hB, base + 1);
        float c2 = __shfl_sync(FULL, hB, base + 2);

        // ---- Layer 0 (chain A) ----
        float g0r = fmaf(wh0[0][2], a2, fmaf(wh0[0][1], a1, fmaf(wh0[0][0], a0, bh0[0])));
        float g0z = fmaf(wh0[1][2], a2, fmaf(wh0[1][1], a1, fmaf(wh0[1][0], a0, bh0[1])));
        float g0n = fmaf(wh0[2][2], a2, fmaf(wh0[2][1], a1, fmaf(wh0[2][0], a0, bh0[2])));
        float r0  = sigm(b4.x + g0r);
        float z0  = sigm(b4.y + g0z);
        float n0  = tanh_fast(fmaf(r0, g0n, b4.z));
        float hAn = fmaf(z0, hA - n0, n0);

        // ---- Layer 1, step t-1 (chain B, independent of chain A) ----
        float i1r = fmaf(wi1[0][2], a2, fmaf(wi1[0][1], a1, fmaf(wi1[0][0], a0, bi1[0])));
        float i1z = fmaf(wi1[1][2], a2, fmaf(wi1[1][1], a1, fmaf(wi1[1][0], a0, bi1[1])));
        float i1n = fmaf(wi1[2][2], a2, fmaf(wi1[2][1], a1, fmaf(wi1[2][0], a0, bi1[2])));
        float g1r = fmaf(wh1[0][2], c2, fmaf(wh1[0][1], c1, fmaf(wh1[0][0], c0, bh1[0])));
        float g1z = fmaf(wh1[1][2], c2, fmaf(wh1[1][1], c1, fmaf(wh1[1][0], c0, bh1[1])));
        float g1n = fmaf(wh1[2][2], c2, fmaf(wh1[2][1], c1, fmaf(wh1[2][0], c0, bh1[2])));
        float r1  = sigm(i1r + g1r);
        float z1  = sigm(i1z + g1z);
        float n1  = tanh_fast(fmaf(r1, g1n, i1n));
        float hBn = fmaf(z1, hB - n1, n1);

        hA = hAn;
        hB = (t == 0) ? 0.f : hBn;   // pipeline bubble at t=0
    }

    // Epilogue: layer-1 consumes h0^{T-1}.
    {
        float a0 = __shfl_sync(FULL, hA, base + 0);
        float a1 = __shfl_sync(FULL, hA, base + 1);
        float a2 = __shfl_sync(FULL, hA, base + 2);
        float c0 = __shfl_sync(FULL, hB, base + 0);
        float c1 = __shfl_sync(FULL, hB, base + 1);
        float c2 = __shfl_sync(FULL, hB, base + 2);

        float i1r = fmaf(wi1[0][2], a2, fmaf(wi1[0][1], a1, fmaf(wi1[0][0], a0, bi1[0])));
        float i1z = fmaf(wi1[1][2], a2, fmaf(wi1[1][1], a1, fmaf(wi1[1][0], a0, bi1[1])));
        float i1n = fmaf(wi1[2][2], a2, fmaf(wi1[2][1], a1, fmaf(wi1[2][0], a0, bi1[2])));
        float g1r = fmaf(wh1[0][2], c2, fmaf(wh1[0][1], c1, fmaf(wh1[0][0], c0, bh1[0])));
        float g1z = fmaf(wh1[1][2], c2, fmaf(wh1[1][1], c1, fmaf(wh1[1][0], c0, bh1[1])));
        float g1n = fmaf(wh1[2][2], c2, fmaf(wh1[2][1], c1, fmaf(wh1[2][0], c0, bh1[2])));
        float r1  = sigm(i1r + g1r);
        float z1  = sigm(i1z + g1z);
        float n1  = tanh_fast(fmaf(r1, g1n, i1n));
        hB = fmaf(z1, hB - n1, n1);
    }

    if (j < 3)
        out[e * 3 + j] = hB;
}

extern "C" void kernel_launch(void* const* d_in, const int* in_sizes, int n_in,
                              void* d_out, int out_size)
{
    const float* x     = (const float*)d_in[0];
    const float* W_ih0 = (const float*)d_in[1];
    const float* W_hh0 = (const float*)d_in[2];
    const float* b_ih0 = (const float*)d_in[3];
    const float* b_hh0 = (const float*)d_in[4];
    const float* W_ih1 = (const float*)d_in[5];
    const float* W_hh1 = (const float*)d_in[6];
    const float* b_ih1 = (const float*)d_in[7];
    const float* b_hh1 = (const float*)d_in[8];
    float* out = (float*)d_out;

    // 128 b-tiles x 64 t-tiles, 128 threads = one per (b,t) cell
    phaseA<<<8192, 128>>>(x, W_ih0, b_ih0);
    // 4 lanes per element -> 8192 threads -> 256 single-warp blocks
    gru_rec<<<256, 32>>>(W_hh0, b_hh0, W_ih1, b_ih1, W_hh1, b_hh1, out);
}

// round 12
// speedup vs baseline: 1.9562x; 1.1601x over previous
#include <cuda_runtime.h>

#define BB 2048
#define TT 512
#define II 64
#define NCHUNK 64        // 64 chunks of 8 timesteps
#define CONS_BLK 64      // consumer blocks (bid 0..63)
#define PROD_BLK 8192    // producer blocks (bid 64..8255)

// Scratch [t][g][b] as float4: index (t*3+g)*BB + b holds (xr_g, xz_g, xn_g, 0).
// 8 timesteps of pad beyond t=TT are NEVER written -> stay zero; dummy lanes
// point at the pad with stride 0.
__device__ float4 g_xw4[(size_t)(TT + 8) * 3 * BB];
#define PAD_OFF ((size_t)TT * 3 * BB)

// Per-chunk completion counters (producer b-tiles done). Reset every launch.
__device__ int g_flags[NCHUNK];

__device__ __forceinline__ float sigm(float x) {
    return __fdividef(1.0f, 1.0f + __expf(-x));
}
__device__ __forceinline__ float tanh_fast(float x) {
    float xc = fmaxf(x, -20.0f);
    float e = __expf(-2.0f * xc);
    return __fdividef(1.0f - e, 1.0f + e);
}

__device__ __forceinline__ int acq_load(const int* p) {
    int v;
    asm volatile("ld.acquire.gpu.b32 %0, [%1];" : "=r"(v) : "l"(p) : "memory");
    return v;
}

__global__ void reset_flags() {
    if (threadIdx.x < NCHUNK) g_flags[threadIdx.x] = 0;
}

// ---------------------------------------------------------------------------
// Fused kernel. bid < CONS_BLK: recurrence consumers (4 warps, 8 elem/warp).
// bid >= CONS_BLK: phaseA producers (16 b x 8 t tile, one thread per cell).
// ---------------------------------------------------------------------------
__global__ void __launch_bounds__(128) fused(
    const float* __restrict__ x,
    const float* __restrict__ W_ih0, const float* __restrict__ b_ih0,
    const float* __restrict__ W_hh0, const float* __restrict__ b_hh0,
    const float* __restrict__ W_ih1, const float* __restrict__ b_ih1,
    const float* __restrict__ W_hh1, const float* __restrict__ b_hh1,
    float* __restrict__ out)
{
    __shared__ float4 xs[16 * 129];   // producer: [b][8t*16f4], b-stride 129
    __shared__ float4 os[24 * 16];    // producer: [(t*3+g)][b]
    __shared__ float4 ws4[144];       // producer: W_ih0 as [9][16] float4
    __shared__ float  bs[9];

    const int tx = threadIdx.x;

    if (blockIdx.x >= CONS_BLK) {
        // =============== PRODUCER (phaseA tile) ===============
        const int pid = blockIdx.x - CONS_BLK;
        const int b0  = (pid & 127) << 4;    // b-tile
        const int cnk = pid >> 7;            // t-chunk 0..63 (bid order = t order)
        const int t0  = cnk << 3;

        if (tx < 128) ws4[tx] = ((const float4*)W_ih0)[tx];
        if (tx < 16)  ws4[128 + tx] = ((const float4*)W_ih0)[128 + tx];
        if (tx < 9)   bs[tx] = b_ih0[tx];

        const float4* xg = (const float4*)x;
#pragma unroll
        for (int c = 0; c < 16; c++) {
            int f   = (c << 7) + tx;
            int bl  = f >> 7;
            int off = f & 127;
            xs[bl * 129 + off] = xg[((size_t)(b0 + bl) * TT + t0) * 16 + off];
        }
        __syncthreads();

        const int b_loc = tx & 15;
        const int t_loc = tx >> 4;

        float acc[9];
#pragma unroll
        for (int g = 0; g < 9; g++) acc[g] = bs[g];
#pragma unroll
        for (int i = 0; i < 16; i++) {
            float4 xv = xs[b_loc * 129 + t_loc * 16 + i];
#pragma unroll
            for (int g = 0; g < 9; g++) {
                float4 wv = ws4[g * 16 + i];
                acc[g] = fmaf(xv.w, wv.w, fmaf(xv.z, wv.z,
                         fmaf(xv.y, wv.y, fmaf(xv.x, wv.x, acc[g]))));
            }
        }
#pragma unroll
        for (int g = 0; g < 3; g++)
            os[(t_loc * 3 + g) * 16 + b_loc] =
                make_float4(acc[g], acc[3 + g], acc[6 + g], 0.f);
        __syncthreads();

#pragma unroll
        for (int r = 0; r < 3; r++) {
            int f    = r * 128 + tx;
            int pair = f >> 4;
            int bl   = f & 15;
            int tt   = pair / 3, gg = pair % 3;
            g_xw4[((size_t)(t0 + tt) * 3 + gg) * BB + b0 + bl] = os[pair * 16 + bl];
        }

        // Release: each thread fences its stores, then one thread signals.
        __threadfence();
        __syncthreads();
        if (tx == 0) atomicAdd(&g_flags[cnk], 1);
        return;
    }

    // =============== CONSUMER (recurrence) ===============
    const int lane = tx & 31;
    const int gw   = blockIdx.x * 4 + (tx >> 5);   // global warp 0..255
    const int j    = lane & 3;
    const int base = lane & ~3;
    const bool dum = (j == 3);
    const int g    = dum ? 0 : j;
    const int e    = gw * 8 + (lane >> 2);

    float wh0[3][3], wi1[3][3], wh1[3][3], bh0[3], bi1[3], bh1[3];
#pragma unroll
    for (int q = 0; q < 3; q++) {
        int row = q * 3 + g;
        bh0[q] = __ldg(b_hh0 + row);
        bi1[q] = __ldg(b_ih1 + row);
        bh1[q] = __ldg(b_hh1 + row);
#pragma unroll
        for (int k = 0; k < 3; k++) {
            wh0[q][k] = __ldg(W_hh0 + row * 3 + k);
            wi1[q][k] = __ldg(W_ih1 + row * 3 + k);
            wh1[q][k] = __ldg(W_hh1 + row * 3 + k);
        }
    }

    float hA = 0.f;   // h0[g]
    float hB = 0.f;   // h1[g]

    const size_t  xstr = dum ? 0 : (size_t)(3 * BB);
    const float4* xb   = g_xw4 + (dum ? PAD_OFF : ((size_t)g * BB + e));

    // Block until chunk 0 is fully produced, then fill the 8-deep ring.
    while (acq_load(&g_flags[0]) < 128) __nanosleep(64);

    float4 buf[8];
#pragma unroll
    for (int s = 0; s < 8; s++) buf[s] = xb[(size_t)s * xstr];

    const unsigned FULL = 0xffffffffu;

    // Software-pipelined readiness check: fv = flags[t8+1] loaded one octet early.
    int fv = acq_load(&g_flags[1]);

    for (int t8 = 0; t8 < 64; t8++) {
        if (t8 < 63) {
            if (fv < 128) {                      // rare post-warmup
                while (acq_load(&g_flags[t8 + 1]) < 128) __nanosleep(64);
            }
            int nxt = (t8 + 2 < 64) ? t8 + 2 : 63;
            fv = acq_load(&g_flags[nxt]);        // for next octet; latency hidden
        }

#pragma unroll
        for (int i = 0; i < 8; i++) {
            const int t = t8 * 8 + i;
            float4 b4 = buf[i];
            buf[i] = xb[(size_t)(t + 8) * xstr];   // t+8 <= 519, inside pad

            float a0 = __shfl_sync(FULL, hA, base + 0);   // h0^{t-1}
            float a1 = __shfl_sync(FULL, hA, base + 1);
            float a2 = __shfl_sync(FULL, hA, base + 2);
            float c0 = __shfl_sync(FULL, hB, base + 0);   // h1^{t-2}
            float c1 = __shfl_sync(FULL, hB, base + 1);
            float c2 = __shfl_sync(FULL, hB, base + 2);

            // ---- Layer 0 (chain A) ----
            float g0r = fmaf(wh0[0][2], a2, fmaf(wh0[0][1], a1, fmaf(wh0[0][0], a0, bh0[0])));
            float g0z = fmaf(wh0[1][2], a2, fmaf(wh0[1][1], a1, fmaf(wh0[1][0], a0, bh0[1])));
            float g0n = fmaf(wh0[2][2], a2, fmaf(wh0[2][1], a1, fmaf(wh0[2][0], a0, bh0[2])));
            float r0  = sigm(b4.x + g0r);
            float z0  = sigm(b4.y + g0z);
            float n0  = tanh_fast(fmaf(r0, g0n, b4.z));
            float hAn = fmaf(z0, hA - n0, n0);

            // ---- Layer 1, step t-1 (chain B) ----
            float i1r = fmaf(wi1[0][2], a2, fmaf(wi1[0][1], a1, fmaf(wi1[0][0], a0, bi1[0])));
            float i1z = fmaf(wi1[1][2], a2, fmaf(wi1[1][1], a1, fmaf(wi1[1][0], a0, bi1[1])));
            float i1n = fmaf(wi1[2][2], a2, fmaf(wi1[2][1], a1, fmaf(wi1[2][0], a0, bi1[2])));
            float g1r = fmaf(wh1[0][2], c2, fmaf(wh1[0][1], c1, fmaf(wh1[0][0], c0, bh1[0])));
            float g1z = fmaf(wh1[1][2], c2, fmaf(wh1[1][1], c1, fmaf(wh1[1][0], c0, bh1[1])));
            float g1n = fmaf(wh1[2][2], c2, fmaf(wh1[2][1], c1, fmaf(wh1[2][0], c0, bh1[2])));
            float r1  = sigm(i1r + g1r);
            float z1  = sigm(i1z + g1z);
            float n1  = tanh_fast(fmaf(r1, g1n, i1n));
            float hBn = fmaf(z1, hB - n1, n1);

            hA = hAn;
            hB = (t == 0) ? 0.f : hBn;   // pipeline bubble at t=0
        }
    }

    // Epilogue: layer-1 consumes h0^{T-1}.
    {
        float a0 = __shfl_sync(FULL, hA, base + 0);
        float a1 = __shfl_sync(FULL, hA, base + 1);
        float a2 = __shfl_sync(FULL, hA, base + 2);
        float c0 = __shfl_sync(FULL, hB, base + 0);
        float c1 = __shfl_sync(FULL, hB, base + 1);
        float c2 = __shfl_sync(FULL, hB, base + 2);

        float i1r = fmaf(wi1[0][2], a2, fmaf(wi1[0][1], a1, fmaf(wi1[0][0], a0, bi1[0])));
        float i1z = fmaf(wi1[1][2], a2, fmaf(wi1[1][1], a1, fmaf(wi1[1][0], a0, bi1[1])));
        float i1n = fmaf(wi1[2][2], a2, fmaf(wi1[2][1], a1, fmaf(wi1[2][0], a0, bi1[2])));
        float g1r = fmaf(wh1[0][2], c2, fmaf(wh1[0][1], c1, fmaf(wh1[0][0], c0, bh1[0])));
        float g1z = fmaf(wh1[1][2], c2, fmaf(wh1[1][1], c1, fmaf(wh1[1][0], c0, bh1[1])));
        float g1n = fmaf(wh1[2][2], c2, fmaf(wh1[2][1], c1, fmaf(wh1[2][0], c0, bh1[2])));
        float r1  = sigm(i1r + g1r);
        float z1  = sigm(i1z + g1z);
        float n1  = tanh_fast(fmaf(r1, g1n, i1n));
        hB = fmaf(z1, hB - n1, n1);
    }

    if (j < 3)
        out[e * 3 + j] = hB;
}

extern "C" void kernel_launch(void* const* d_in, const int* in_sizes, int n_in,
                              void* d_out, int out_size)
{
    const float* x     = (const float*)d_in[0];
    const float* W_ih0 = (const float*)d_in[1];
    const float* W_hh0 = (const float*)d_in[2];
    const float* b_ih0 = (const float*)d_in[3];
    const float* b_hh0 = (const float*)d_in[4];
    const float* W_ih1 = (const float*)d_in[5];
    const float* W_hh1 = (const float*)d_in[6];
    const float* b_ih1 = (const float*)d_in[7];
    const float* b_hh1 = (const float*)d_in[8];
    float* out = (float*)d_out;

    reset_flags<<<1, 64>>>();
    fused<<<CONS_BLK + PROD_BLK, 128>>>(
        x, W_ih0, b_ih0, W_hh0, b_hh0, W_ih1, b_ih1, W_hh1, b_hh1, out);
}

// round 13
// speedup vs baseline: 2.1318x; 1.0898x over previous
#include <cuda_runtime.h>

#define BB 2048
#define TT 512
#define II 64
#define NCHUNK 64        // 64 flag-chunks of 8 timesteps
#define CONS_BLK 64      // consumer blocks (bid 0..63)
#define PROD_BLK 4096    // producer blocks: 128 b-tiles x 32 t-tiles (16 t each)

#define XS_STRIDE 257    // float4 per b-row in dynamic smem (16t*16f4 + 1 pad)
#define XS_BYTES  (16 * XS_STRIDE * 16)   // 65,792 bytes

// Scratch [t][g][b] as float4: index (t*3+g)*BB + b holds (xr_g, xz_g, xn_g, 0).
// 8 timesteps of pad beyond t=TT are NEVER written -> stay zero; dummy lanes
// point at the pad with stride 0.
__device__ float4 g_xw4[(size_t)(TT + 8) * 3 * BB];
#define PAD_OFF ((size_t)TT * 3 * BB)

// Per-8t-chunk completion counters (128 b-tiles each). Reset every launch.
__device__ int g_flags[NCHUNK];

__device__ __forceinline__ float sigm(float x) {
    return __fdividef(1.0f, 1.0f + __expf(-x));
}
__device__ __forceinline__ float tanh_fast(float x) {
    float xc = fmaxf(x, -20.0f);
    float e = __expf(-2.0f * xc);
    return __fdividef(1.0f - e, 1.0f + e);
}
__device__ __forceinline__ int acq_load(const int* p) {
    int v;
    asm volatile("ld.acquire.gpu.b32 %0, [%1];" : "=r"(v) : "l"(p) : "memory");
    return v;
}

__global__ void reset_flags() {
    if (threadIdx.x < NCHUNK) g_flags[threadIdx.x] = 0;
}

// ---------------------------------------------------------------------------
// Fused kernel. bid < CONS_BLK: recurrence consumers (4 warps, 8 elem/warp).
// bid >= CONS_BLK: phaseA producers: 16b x 16t tile, 128 threads, each thread
// computes TWO consecutive t-cells (weight LDS amortized 2x). ~79KB smem per
// block -> 2 blocks/SM -> at most ONE producer block beside each consumer.
// ---------------------------------------------------------------------------
__global__ void __launch_bounds__(128) fused(
    const float* __restrict__ x,
    const float* __restrict__ W_ih0, const float* __restrict__ b_ih0,
    const float* __restrict__ W_hh0, const float* __restrict__ b_hh0,
    const float* __restrict__ W_ih1, const float* __restrict__ b_ih1,
    const float* __restrict__ W_hh1, const float* __restrict__ b_hh1,
    float* __restrict__ out)
{
    extern __shared__ float4 xs[];    // [16 b][XS_STRIDE] (dynamic, 64.25 KB)
    __shared__ float4 os[48 * 16];    // [(t*3+g)][b]
    __shared__ float4 ws4[144];       // W_ih0 as [9][16] float4
    __shared__ float  bs[9];

    const int tx = threadIdx.x;

    if (blockIdx.x >= CONS_BLK) {
        // =============== PRODUCER ===============
        const int pid = blockIdx.x - CONS_BLK;
        const int b0  = (pid & 127) << 4;    // b-tile (fastest -> chunk 0 first)
        const int cnk = pid >> 7;            // 16-t tile index 0..31
        const int t0  = cnk << 4;

        if (tx < 128) ws4[tx] = ((const float4*)W_ih0)[tx];
        if (tx < 16)  ws4[128 + tx] = ((const float4*)W_ih0)[128 + tx];
        if (tx < 9)   bs[tx] = b_ih0[tx];

        // Stage 16 b-rows x 16 t x 16 f4 (4 KB contiguous per b-row).
        const float4* xg = (const float4*)x;
#pragma unroll
        for (int c = 0; c < 32; c++) {
            int f   = (c << 7) + tx;         // 0..4095
            int bl  = f >> 8;                // 256 f4 per b-row
            int off = f & 255;
            xs[bl * XS_STRIDE + off] = xg[((size_t)(b0 + bl) * TT + t0) * 16 + off];
        }
        __syncthreads();

        const int b_loc = tx & 15;
        const int tp    = tx >> 4;           // 0..7 -> t-cells 2tp, 2tp+1
        const int tl0   = tp * 2;

        float acc0[9], acc1[9];
#pragma unroll
        for (int g = 0; g < 9; g++) { acc0[g] = bs[g]; acc1[g] = bs[g]; }

#pragma unroll
        for (int i = 0; i < 16; i++) {
            float4 xv0 = xs[b_loc * XS_STRIDE + tl0 * 16 + i];
            float4 xv1 = xs[b_loc * XS_STRIDE + (tl0 + 1) * 16 + i];
#pragma unroll
            for (int g = 0; g < 9; g++) {
                float4 wv = ws4[g * 16 + i];
                acc0[g] = fmaf(xv0.w, wv.w, fmaf(xv0.z, wv.z,
                          fmaf(xv0.y, wv.y, fmaf(xv0.x, wv.x, acc0[g]))));
                acc1[g] = fmaf(xv1.w, wv.w, fmaf(xv1.z, wv.z,
                          fmaf(xv1.y, wv.y, fmaf(xv1.x, wv.x, acc1[g]))));
            }
        }

#pragma unroll
        for (int g = 0; g < 3; g++) {
            os[(tl0 * 3 + g) * 16 + b_loc] =
                make_float4(acc0[g], acc0[3 + g], acc0[6 + g], 0.f);
            os[((tl0 + 1) * 3 + g) * 16 + b_loc] =
                make_float4(acc1[g], acc1[3 + g], acc1[6 + g], 0.f);
        }
        __syncthreads();

        // 768 float4 out, 128 threads x 6 rounds, lanes consecutive in b.
#pragma unroll
        for (int r = 0; r < 6; r++) {
            int f    = r * 128 + tx;
            int pair = f >> 4;               // tt*3 + g  (0..47)
            int bl   = f & 15;
            int tt   = pair / 3, gg = pair % 3;
            g_xw4[((size_t)(t0 + tt) * 3 + gg) * BB + b0 + bl] = os[pair * 16 + bl];
        }

        __threadfence();
        __syncthreads();
        if (tx == 0) {                       // tile spans 8t-chunks 2cnk, 2cnk+1
            atomicAdd(&g_flags[2 * cnk], 1);
            atomicAdd(&g_flags[2 * cnk + 1], 1);
        }
        return;
    }

    // =============== CONSUMER (unchanged math) ===============
    const int lane = tx & 31;
    const int gw   = blockIdx.x * 4 + (tx >> 5);   // global warp 0..255
    const int j    = lane & 3;
    const int base = lane & ~3;
    const bool dum = (j == 3);
    const int g    = dum ? 0 : j;
    const int e    = gw * 8 + (lane >> 2);

    float wh0[3][3], wi1[3][3], wh1[3][3], bh0[3], bi1[3], bh1[3];
#pragma unroll
    for (int q = 0; q < 3; q++) {
        int row = q * 3 + g;
        bh0[q] = __ldg(b_hh0 + row);
        bi1[q] = __ldg(b_ih1 + row);
        bh1[q] = __ldg(b_hh1 + row);
#pragma unroll
        for (int k = 0; k < 3; k++) {
            wh0[q][k] = __ldg(W_hh0 + row * 3 + k);
            wi1[q][k] = __ldg(W_ih1 + row * 3 + k);
            wh1[q][k] = __ldg(W_hh1 + row * 3 + k);
        }
    }

    float hA = 0.f;   // h0[g]
    float hB = 0.f;   // h1[g]

    const size_t  xstr = dum ? 0 : (size_t)(3 * BB);
    const float4* xb   = g_xw4 + (dum ? PAD_OFF : ((size_t)g * BB + e));

    while (acq_load(&g_flags[0]) < 128) __nanosleep(64);

    float4 buf[8];
#pragma unroll
    for (int s = 0; s < 8; s++) buf[s] = xb[(size_t)s * xstr];

    const unsigned FULL = 0xffffffffu;

    int fv = acq_load(&g_flags[1]);

    for (int t8 = 0; t8 < 64; t8++) {
        if (t8 < 63) {
            if (fv < 128) {
                while (acq_load(&g_flags[t8 + 1]) < 128) __nanosleep(64);
            }
            int nxt = (t8 + 2 < 64) ? t8 + 2 : 63;
            fv = acq_load(&g_flags[nxt]);
        }

#pragma unroll
        for (int i = 0; i < 8; i++) {
            const int t = t8 * 8 + i;
            float4 b4 = buf[i];
            buf[i] = xb[(size_t)(t + 8) * xstr];

            float a0 = __shfl_sync(FULL, hA, base + 0);
            float a1 = __shfl_sync(FULL, hA, base + 1);
            float a2 = __shfl_sync(FULL, hA, base + 2);
            float c0 = __shfl_sync(FULL, hB, base + 0);
            float c1 = __shfl_sync(FULL, hB, base + 1);
            float c2 = __shfl_sync(FULL, hB, base + 2);

            float g0r = fmaf(wh0[0][2], a2, fmaf(wh0[0][1], a1, fmaf(wh0[0][0], a0, bh0[0])));
            float g0z = fmaf(wh0[1][2], a2, fmaf(wh0[1][1], a1, fmaf(wh0[1][0], a0, bh0[1])));
            float g0n = fmaf(wh0[2][2], a2, fmaf(wh0[2][1], a1, fmaf(wh0[2][0], a0, bh0[2])));
            float r0  = sigm(b4.x + g0r);
            float z0  = sigm(b4.y + g0z);
            float n0  = tanh_fast(fmaf(r0, g0n, b4.z));
            float hAn = fmaf(z0, hA - n0, n0);

            float i1r = fmaf(wi1[0][2], a2, fmaf(wi1[0][1], a1, fmaf(wi1[0][0], a0, bi1[0])));
            float i1z = fmaf(wi1[1][2], a2, fmaf(wi1[1][1], a1, fmaf(wi1[1][0], a0, bi1[1])));
            float i1n = fmaf(wi1[2][2], a2, fmaf(wi1[2][1], a1, fmaf(wi1[2][0], a0, bi1[2])));
            float g1r = fmaf(wh1[0][2], c2, fmaf(wh1[0][1], c1, fmaf(wh1[0][0], c0, bh1[0])));
            float g1z = fmaf(wh1[1][2], c2, fmaf(wh1[1][1], c1, fmaf(wh1[1][0], c0, bh1[1])));
            float g1n = fmaf(wh1[2][2], c2, fmaf(wh1[2][1], c1, fmaf(wh1[2][0], c0, bh1[2])));
            float r1  = sigm(i1r + g1r);
            float z1  = sigm(i1z + g1z);
            float n1  = tanh_fast(fmaf(r1, g1n, i1n));
            float hBn = fmaf(z1, hB - n1, n1);

            hA = hAn;
            hB = (t == 0) ? 0.f : hBn;
        }
    }

    // Epilogue: layer-1 consumes h0^{T-1}.
    {
        float a0 = __shfl_sync(FULL, hA, base + 0);
        float a1 = __shfl_sync(FULL, hA, base + 1);
        float a2 = __shfl_sync(FULL, hA, base + 2);
        float c0 = __shfl_sync(FULL, hB, base + 0);
        float c1 = __shfl_sync(FULL, hB, base + 1);
        float c2 = __shfl_sync(FULL, hB, base + 2);

        float i1r = fmaf(wi1[0][2], a2, fmaf(wi1[0][1], a1, fmaf(wi1[0][0], a0, bi1[0])));
        float i1z = fmaf(wi1[1][2], a2, fmaf(wi1[1][1], a1, fmaf(wi1[1][0], a0, bi1[1])));
        float i1n = fmaf(wi1[2][2], a2, fmaf(wi1[2][1], a1, fmaf(wi1[2][0], a0, bi1[2])));
        float g1r = fmaf(wh1[0][2], c2, fmaf(wh1[0][1], c1, fmaf(wh1[0][0], c0, bh1[0])));
        float g1z = fmaf(wh1[1][2], c2, fmaf(wh1[1][1], c1, fmaf(wh1[1][0], c0, bh1[1])));
        float g1n = fmaf(wh1[2][2], c2, fmaf(wh1[2][1], c1, fmaf(wh1[2][0], c0, bh1[2])));
        float r1  = sigm(i1r + g1r);
        float z1  = sigm(i1z + g1z);
        float n1  = tanh_fast(fmaf(r1, g1n, i1n));
        hB = fmaf(z1, hB - n1, n1);
    }

    if (j < 3)
        out[e * 3 + j] = hB;
}

extern "C" void kernel_launch(void* const* d_in, const int* in_sizes, int n_in,
                              void* d_out, int out_size)
{
    const float* x     = (const float*)d_in[0];
    const float* W_ih0 = (const float*)d_in[1];
    const float* W_hh0 = (const float*)d_in[2];
    const float* b_ih0 = (const float*)d_in[3];
    const float* b_hh0 = (const float*)d_in[4];
    const float* W_ih1 = (const float*)d_in[5];
    const float* W_hh1 = (const float*)d_in[6];
    const float* b_ih1 = (const float*)d_in[7];
    const float* b_hh1 = (const float*)d_in[8];
    float* out = (float*)d_out;

    cudaFuncSetAttribute(fused, cudaFuncAttributeMaxDynamicSharedMemorySize, XS_BYTES);

    reset_flags<<<1, 64>>>();
    fused<<<CONS_BLK + PROD_BLK, 128, XS_BYTES>>>(
        x, W_ih0, b_ih0, W_hh0, b_hh0, W_ih1, b_ih1, W_hh1, b_hh1, out);
}